// round 3
// baseline (speedup 1.0000x reference)
#include <cuda_runtime.h>
#include <cuda_bf16.h>

#define BS 128
#define NN 32
#define IN_DIM 16
#define HID 128
#define HEADS 4
#define OUTD 5
#define DUEL_H 256
#define D1 (HEADS*HID)       // 512
#define LATENT (HID + 2*D1)  // 1152
#define OBS_W (NN*(2+IN_DIM)+1) // 577
#define RAD2 0.09f

// -------- scratch (device globals; no runtime alloc allowed) --------
__device__ float g_X0 [BS*NN*HID];   // encoder out
__device__ unsigned g_ADJ[BS*NN];    // adjacency bitmask per row
__device__ float g_GL1[BS*NN*D1];
__device__ float g_GR1[BS*NN*D1];
__device__ float g_X1 [BS*NN*D1];    // relu(gat1)
__device__ float g_GL2[BS*NN*D1];
__device__ float g_GR2[BS*NN*D1];
__device__ float g_X2 [BS*NN*D1];    // relu(gat2)

// -------- encoder + adjacency: one block per batch, 128 threads --------
__global__ void enc_kernel(const float* __restrict__ obs,
                           const float* __restrict__ w1, const float* __restrict__ b1,
                           const float* __restrict__ w2, const float* __restrict__ b2,
                           float* __restrict__ X0, unsigned* __restrict__ ADJ)
{
    __shared__ float s_obs[OBS_W];
    __shared__ float s_h[NN*HID];
    int b = blockIdx.x, t = threadIdx.x;

    for (int i = t; i < OBS_W; i += 128) s_obs[i] = obs[b*OBS_W + i];
    __syncthreads();

    // adjacency bitmask (threads 0..31)
    if (t < NN) {
        float xi = s_obs[t*18 + 0], yi = s_obs[t*18 + 1];
        unsigned m = 0;
        #pragma unroll
        for (int j = 0; j < NN; j++) {
            float dx = xi - s_obs[j*18 + 0];
            float dy = yi - s_obs[j*18 + 1];
            float d2 = dx*dx + dy*dy;
            if (d2 < RAD2 || j == t) m |= (1u << j);
        }
        ADJ[b*NN + t] = m;
    }

    // h = relu(feats @ w1 + b1); thread t = output column
    float bb = b1[t];
    for (int r = 0; r < NN; r++) {
        float acc = bb;
        #pragma unroll
        for (int f = 0; f < IN_DIM; f++)
            acc += s_obs[r*18 + 2 + f] * w1[f*HID + t];
        s_h[r*HID + t] = fmaxf(acc, 0.f);
    }
    __syncthreads();

    // x = relu(h @ w2 + b2)
    float b2v = b2[t];
    for (int r = 0; r < NN; r++) {
        float acc = b2v;
        #pragma unroll 8
        for (int k = 0; k < HID; k++)
            acc += s_h[r*HID + k] * w2[k*HID + t];
        X0[(b*NN + r)*HID + t] = fmaxf(acc, 0.f);
    }
}

// -------- GEMM: Y(BS*32, 512) = X(BS*32, DIN) @ W(DIN, 512) --------
// grid (BS, 2), 128 threads; each thread computes 2 cols x 32 rows
template<int DIN>
__global__ void gemm_k(const float* __restrict__ X, const float* __restrict__ W,
                       float* __restrict__ Y)
{
    __shared__ float Xs[NN*128];
    int b  = blockIdx.x;
    int c0 = blockIdx.y*256 + threadIdx.x;   // cols c0 and c0+128

    float acc0[NN], acc1[NN];
    #pragma unroll
    for (int r = 0; r < NN; r++) { acc0[r] = 0.f; acc1[r] = 0.f; }

    for (int kb = 0; kb < DIN; kb += 128) {
        __syncthreads();
        for (int i = threadIdx.x; i < NN*128; i += 128) {
            int r = i >> 7, c = i & 127;
            Xs[i] = X[(b*NN + r)*DIN + kb + c];
        }
        __syncthreads();
        #pragma unroll 4
        for (int k = 0; k < 128; k++) {
            float w0 = W[(kb + k)*D1 + c0];
            float w1 = W[(kb + k)*D1 + c0 + 128];
            #pragma unroll
            for (int r = 0; r < NN; r++) {
                float xv = Xs[r*128 + k];
                acc0[r] += xv * w0;
                acc1[r] += xv * w1;
            }
        }
    }
    #pragma unroll
    for (int r = 0; r < NN; r++) {
        Y[(b*NN + r)*D1 + c0]       = acc0[r];
        Y[(b*NN + r)*D1 + c0 + 128] = acc1[r];
    }
}

// -------- GATv2 attention per (batch, head): logits + softmax + aggregate --------
__global__ void attn_k(const float* __restrict__ GL, const float* __restrict__ GR,
                       const unsigned* __restrict__ ADJ,
                       const float* __restrict__ att, const float* __restrict__ bias,
                       float* __restrict__ Xout)
{
    __shared__ float gls[NN*129];
    __shared__ float grs[NN*129];
    __shared__ float lg[NN*NN];
    __shared__ float attv[HID];

    int b = blockIdx.x, h = blockIdx.y, t = threadIdx.x; // 128 threads

    attv[t] = att[h*HID + t];
    for (int i = t; i < NN*HID; i += 128) {
        int r = i >> 7, c = i & 127;
        gls[r*129 + c] = GL[(b*NN + r)*D1 + h*HID + c];
        grs[r*129 + c] = GR[(b*NN + r)*D1 + h*HID + c];
    }
    __syncthreads();

    // logits[i][j] = sum_c att[c] * leaky(gr[i,c] + gl[j,c]) if adj else -inf
    for (int idx = t; idx < NN*NN; idx += 128) {
        int i = idx >> 5, j = idx & 31;
        unsigned m = ADJ[b*NN + i];
        float s;
        if ((m >> j) & 1u) {
            s = 0.f;
            #pragma unroll 8
            for (int c = 0; c < HID; c++) {
                float v = grs[i*129 + c] + gls[j*129 + c];
                v = v > 0.f ? v : 0.2f * v;
                s += attv[c] * v;
            }
        } else {
            s = -1e30f;
        }
        lg[idx] = s;
    }
    __syncthreads();

    // softmax over j (threads 0..31, one row each)
    if (t < NN) {
        float mx = -1e30f;
        #pragma unroll
        for (int j = 0; j < NN; j++) mx = fmaxf(mx, lg[t*NN + j]);
        float e[NN], sum = 0.f;
        #pragma unroll
        for (int j = 0; j < NN; j++) { e[j] = expf(lg[t*NN + j] - mx); sum += e[j]; }
        float inv = 1.f / sum;
        #pragma unroll
        for (int j = 0; j < NN; j++) lg[t*NN + j] = e[j] * inv;
    }
    __syncthreads();

    // out[i][c] = relu(sum_j alpha[i][j] * gl[j][c] + bias); thread t = channel
    float bv = bias[h*HID + t];
    for (int i = 0; i < NN; i++) {
        float acc = 0.f;
        #pragma unroll
        for (int j = 0; j < NN; j++)
            acc += lg[i*NN + j] * gls[j*129 + t];
        Xout[(b*NN + i)*D1 + h*HID + t] = fmaxf(acc + bv, 0.f);
    }
}

// -------- dueling head: gather latent + 2-layer MLPs + advantage combine --------
__global__ void head_k(const float* __restrict__ obs,
                       const float* __restrict__ X0, const float* __restrict__ X1,
                       const float* __restrict__ X2,
                       const float* __restrict__ qw1, const float* __restrict__ qb1,
                       const float* __restrict__ qw2, const float* __restrict__ qb2,
                       const float* __restrict__ vw1, const float* __restrict__ vb1,
                       const float* __restrict__ vw2, const float* __restrict__ vb2,
                       float* __restrict__ out)
{
    __shared__ float xc[LATENT];
    __shared__ float qh[DUEL_H], vh[DUEL_H];
    __shared__ float qv[OUTD];
    __shared__ float vscal;

    int b = blockIdx.x, t = threadIdx.x; // 256 threads
    float av = obs[b*OBS_W + (OBS_W - 1)];
    av = fminf(fmaxf(av, 0.f), 31.f);
    int a = (int)av;

    if (t < HID) xc[t] = X0[(b*NN + a)*HID + t];
    for (int i = t; i < D1; i += 256) {
        xc[HID + i]      = X1[(b*NN + a)*D1 + i];
        xc[HID + D1 + i] = X2[(b*NN + a)*D1 + i];
    }
    __syncthreads();

    float aq = qb1[t], avv = vb1[t];
    #pragma unroll 8
    for (int k = 0; k < LATENT; k++) {
        float xv = xc[k];
        aq  += xv * qw1[k*DUEL_H + t];
        avv += xv * vw1[k*DUEL_H + t];
    }
    qh[t] = fmaxf(aq, 0.f);
    vh[t] = fmaxf(avv, 0.f);
    __syncthreads();

    if (t < OUTD) {
        float s = qb2[t];
        for (int k = 0; k < DUEL_H; k++) s += qh[k] * qw2[k*OUTD + t];
        qv[t] = s;
    }
    if (t == 8) {
        float s = vb2[0];
        for (int k = 0; k < DUEL_H; k++) s += vh[k] * vw2[k];
        vscal = s;
    }
    __syncthreads();

    if (t < OUTD) {
        float m = (qv[0] + qv[1] + qv[2] + qv[3] + qv[4]) * 0.2f;
        out[b*OUTD + t] = qv[t] - m + vscal;
    }
}

extern "C" void kernel_launch(void* const* d_in, const int* in_sizes, int n_in,
                              void* d_out, int out_size)
{
    const float* obs    = (const float*)d_in[0];
    const float* enc_w1 = (const float*)d_in[1];
    const float* enc_b1 = (const float*)d_in[2];
    const float* enc_w2 = (const float*)d_in[3];
    const float* enc_b2 = (const float*)d_in[4];
    const float* wl1    = (const float*)d_in[5];
    const float* wr1    = (const float*)d_in[6];
    const float* att1   = (const float*)d_in[7];
    const float* bias1  = (const float*)d_in[8];
    const float* wl2    = (const float*)d_in[9];
    const float* wr2    = (const float*)d_in[10];
    const float* att2   = (const float*)d_in[11];
    const float* bias2  = (const float*)d_in[12];
    const float* q_w1   = (const float*)d_in[13];
    const float* q_b1   = (const float*)d_in[14];
    const float* q_w2   = (const float*)d_in[15];
    const float* q_b2   = (const float*)d_in[16];
    const float* v_w1   = (const float*)d_in[17];
    const float* v_b1   = (const float*)d_in[18];
    const float* v_w2   = (const float*)d_in[19];
    const float* v_b2   = (const float*)d_in[20];
    float* out = (float*)d_out;

    float* X0;  cudaGetSymbolAddress((void**)&X0,  g_X0);
    unsigned* ADJ; cudaGetSymbolAddress((void**)&ADJ, g_ADJ);
    float* GL1; cudaGetSymbolAddress((void**)&GL1, g_GL1);
    float* GR1; cudaGetSymbolAddress((void**)&GR1, g_GR1);
    float* X1;  cudaGetSymbolAddress((void**)&X1,  g_X1);
    float* GL2; cudaGetSymbolAddress((void**)&GL2, g_GL2);
    float* GR2; cudaGetSymbolAddress((void**)&GR2, g_GR2);
    float* X2;  cudaGetSymbolAddress((void**)&X2,  g_X2);

    enc_kernel<<<BS, 128>>>(obs, enc_w1, enc_b1, enc_w2, enc_b2, X0, ADJ);

    gemm_k<HID><<<dim3(BS, 2), 128>>>(X0, wl1, GL1);
    gemm_k<HID><<<dim3(BS, 2), 128>>>(X0, wr1, GR1);
    attn_k<<<dim3(BS, HEADS), 128>>>(GL1, GR1, ADJ, att1, bias1, X1);

    gemm_k<D1><<<dim3(BS, 2), 128>>>(X1, wl2, GL2);
    gemm_k<D1><<<dim3(BS, 2), 128>>>(X1, wr2, GR2);
    attn_k<<<dim3(BS, HEADS), 128>>>(GL2, GR2, ADJ, att2, bias2, X2);

    head_k<<<BS, 256>>>(obs, X0, X1, X2,
                        q_w1, q_b1, q_w2, q_b2,
                        v_w1, v_b1, v_w2, v_b2, out);
}

// round 4
// speedup vs baseline: 1.0257x; 1.0257x over previous
#include <cuda_runtime.h>
#include <cuda_bf16.h>

#define BS 128
#define NN 32
#define IN_DIM 16
#define HID 128
#define HEADS 4
#define OUTD 5
#define DUEL_H 256
#define D1 (HEADS*HID)       // 512
#define LATENT (HID + 2*D1)  // 1152
#define OBS_W (NN*(2+IN_DIM)+1) // 577
#define RAD2 0.09f

typedef unsigned long long ull;

__device__ __forceinline__ ull pack2(float v) {
    ull r; asm("mov.b64 %0, {%1, %1};" : "=l"(r) : "f"(v)); return r;
}
__device__ __forceinline__ void fma2(ull& d, ull a, ull b) {
    asm("fma.rn.f32x2 %0, %1, %2, %0;" : "+l"(d) : "l"(a), "l"(b));
}
__device__ __forceinline__ float2 unpack2(ull v) {
    float2 r; asm("mov.b64 {%0, %1}, %2;" : "=f"(r.x), "=f"(r.y) : "l"(v)); return r;
}

// -------- scratch (device globals; no runtime alloc allowed) --------
__device__ float g_X0 [BS*NN*HID];   // encoder out
__device__ unsigned g_ADJ[BS*NN];    // adjacency bitmask per row
__device__ float g_GL1[BS*NN*D1];
__device__ float g_GR1[BS*NN*D1];
__device__ float g_X1 [BS*NN*D1];    // relu(gat1)
__device__ float g_GL2[BS*NN*D1];
__device__ float g_GR2[BS*NN*D1];
__device__ float g_X2 [BS*NN*D1];    // relu(gat2)
__device__ float g_QH [BS*DUEL_H];
__device__ float g_VH [BS*DUEL_H];

// -------- encoder + adjacency: one block per batch, 128 threads --------
__global__ void enc_kernel(const float* __restrict__ obs,
                           const float* __restrict__ w1, const float* __restrict__ b1,
                           const float* __restrict__ w2, const float* __restrict__ b2,
                           float* __restrict__ X0, unsigned* __restrict__ ADJ)
{
    __shared__ float s_obs[OBS_W];
    __shared__ float s_h[NN*HID];
    int b = blockIdx.x, t = threadIdx.x;

    for (int i = t; i < OBS_W; i += 128) s_obs[i] = obs[b*OBS_W + i];
    __syncthreads();

    if (t < NN) {
        float xi = s_obs[t*18 + 0], yi = s_obs[t*18 + 1];
        unsigned m = 0;
        #pragma unroll
        for (int j = 0; j < NN; j++) {
            float dx = xi - s_obs[j*18 + 0];
            float dy = yi - s_obs[j*18 + 1];
            float d2 = dx*dx + dy*dy;
            if (d2 < RAD2 || j == t) m |= (1u << j);
        }
        ADJ[b*NN + t] = m;
    }

    float bb = b1[t];
    for (int r = 0; r < NN; r++) {
        float acc = bb;
        #pragma unroll
        for (int f = 0; f < IN_DIM; f++)
            acc += s_obs[r*18 + 2 + f] * w1[f*HID + t];
        s_h[r*HID + t] = fmaxf(acc, 0.f);
    }
    __syncthreads();

    float b2v = b2[t];
    for (int r = 0; r < NN; r++) {
        float acc = b2v;
        #pragma unroll 8
        for (int k = 0; k < HID; k++)
            acc += s_h[r*HID + k] * w2[k*HID + t];
        X0[(b*NN + r)*HID + t] = fmaxf(acc, 0.f);
    }
}

// -------- fused GL/GR GEMM with packed f32x2 FMA --------
// Y(4096, 512) = X(4096, DIN) @ W(DIN, 512), for W in {WL, WR}.
// grid (32, 8): x = 128-row M tile, y<4 -> WL cols y*128, else WR cols (y-4)*128.
// block 256 threads, thread computes 8 rows x 8 cols (4 f32x2 col-pairs).
template<int DIN>
__global__ void __launch_bounds__(256, 2)
gat_gemm(const float* __restrict__ X,
         const float* __restrict__ WL, const float* __restrict__ WR,
         float* __restrict__ GL, float* __restrict__ GR)
{
    __shared__ float Xs[128][36];
    __shared__ float Ws[32][128];

    int mt = blockIdx.x;
    int yt = blockIdx.y;
    const float* W = (yt < 4) ? WL : WR;
    float* Y = (yt < 4) ? GL : GR;
    int ct = (yt & 3) * 128;

    int t  = threadIdx.x;
    int tx = t & 15, ty = t >> 4;
    int r0 = ty * 8;
    int c0 = tx * 8;

    ull acc[8][4];
    #pragma unroll
    for (int i = 0; i < 8; i++)
        #pragma unroll
        for (int p = 0; p < 4; p++) acc[i][p] = 0ull;

    const float* Xblk = X + (size_t)(mt*128) * DIN;

    for (int kb = 0; kb < DIN; kb += 32) {
        // X tile: 128 x 32 (1024 float4)
        #pragma unroll
        for (int i = t; i < 1024; i += 256) {
            int r = i >> 3, c4 = i & 7;
            float4 v = *(const float4*)(Xblk + r*DIN + kb + c4*4);
            *(float4*)&Xs[r][c4*4] = v;
        }
        // W tile: 32 x 128 (1024 float4)
        #pragma unroll
        for (int i = t; i < 1024; i += 256) {
            int r = i >> 5, c4 = i & 31;
            float4 v = *(const float4*)(W + (size_t)(kb + r)*D1 + ct + c4*4);
            *(float4*)&Ws[r][c4*4] = v;
        }
        __syncthreads();
        #pragma unroll
        for (int k = 0; k < 32; k++) {
            const ull* wp = (const ull*)&Ws[k][c0];
            ull w0 = wp[0], w1 = wp[1], w2 = wp[2], w3 = wp[3];
            #pragma unroll
            for (int i = 0; i < 8; i++) {
                ull xx = pack2(Xs[r0 + i][k]);
                fma2(acc[i][0], xx, w0);
                fma2(acc[i][1], xx, w1);
                fma2(acc[i][2], xx, w2);
                fma2(acc[i][3], xx, w3);
            }
        }
        __syncthreads();
    }

    #pragma unroll
    for (int i = 0; i < 8; i++) {
        int row = mt*128 + r0 + i;
        float2 u0 = unpack2(acc[i][0]);
        float2 u1 = unpack2(acc[i][1]);
        float2 u2 = unpack2(acc[i][2]);
        float2 u3 = unpack2(acc[i][3]);
        float4 a = make_float4(u0.x, u0.y, u1.x, u1.y);
        float4 b = make_float4(u2.x, u2.y, u3.x, u3.y);
        *(float4*)(Y + (size_t)row*D1 + ct + c0)     = a;
        *(float4*)(Y + (size_t)row*D1 + ct + c0 + 4) = b;
    }
}

// -------- GATv2 attention per (batch, head) --------
__global__ void attn_k(const float* __restrict__ GL, const float* __restrict__ GR,
                       const unsigned* __restrict__ ADJ,
                       const float* __restrict__ att, const float* __restrict__ bias,
                       float* __restrict__ Xout)
{
    __shared__ float gls[NN][132];
    __shared__ float grs[NN][132];
    __shared__ float lg[NN*NN];
    __shared__ float attv[HID];

    int b = blockIdx.x, h = blockIdx.y, t = threadIdx.x; // 128 threads
    int w = t >> 5, j = t & 31;

    attv[t] = att[h*HID + t];
    #pragma unroll
    for (int i = t; i < NN*(HID/4); i += 128) {   // 1024 float4s
        int r = i >> 5, c4 = i & 31;
        const float* src = GL + (size_t)(b*NN + r)*D1 + h*HID + c4*4;
        const float* srr = GR + (size_t)(b*NN + r)*D1 + h*HID + c4*4;
        *(float4*)&gls[r][c4*4] = *(const float4*)src;
        *(float4*)&grs[r][c4*4] = *(const float4*)srr;
    }
    __syncthreads();

    // logits: warp w handles rows i = w*8 .. w*8+7, lane j = neighbor
    #pragma unroll
    for (int ii = 0; ii < 8; ii++) {
        int i = w*8 + ii;
        unsigned m = ADJ[b*NN + i];
        float acc = 0.f;
        #pragma unroll 8
        for (int c4 = 0; c4 < 32; c4++) {
            float4 gr4 = *(const float4*)&grs[i][c4*4];
            float4 gl4 = *(const float4*)&gls[j][c4*4];
            float4 a4  = *(const float4*)&attv[c4*4];
            float v;
            v = gr4.x + gl4.x; v = v - 0.8f*fminf(v, 0.f); acc = fmaf(a4.x, v, acc);
            v = gr4.y + gl4.y; v = v - 0.8f*fminf(v, 0.f); acc = fmaf(a4.y, v, acc);
            v = gr4.z + gl4.z; v = v - 0.8f*fminf(v, 0.f); acc = fmaf(a4.z, v, acc);
            v = gr4.w + gl4.w; v = v - 0.8f*fminf(v, 0.f); acc = fmaf(a4.w, v, acc);
        }
        lg[i*NN + j] = ((m >> j) & 1u) ? acc : -1e30f;
    }
    __syncthreads();

    // softmax over j: warp-parallel, 8 rows per warp
    #pragma unroll
    for (int ii = 0; ii < 8; ii++) {
        int i = w*8 + ii;
        float x = lg[i*NN + j];
        float mx = x;
        #pragma unroll
        for (int o = 16; o > 0; o >>= 1) mx = fmaxf(mx, __shfl_xor_sync(0xffffffffu, mx, o));
        float e = __expf(x - mx);
        float s = e;
        #pragma unroll
        for (int o = 16; o > 0; o >>= 1) s += __shfl_xor_sync(0xffffffffu, s, o);
        lg[i*NN + j] = e / s;
    }
    __syncthreads();

    // aggregate: thread t = channel
    float bv = bias[h*HID + t];
    #pragma unroll 4
    for (int i = 0; i < NN; i++) {
        float acc = 0.f;
        #pragma unroll
        for (int j4 = 0; j4 < 8; j4++) {
            float4 al = *(const float4*)&lg[i*NN + j4*4];
            acc = fmaf(al.x, gls[j4*4 + 0][t], acc);
            acc = fmaf(al.y, gls[j4*4 + 1][t], acc);
            acc = fmaf(al.z, gls[j4*4 + 2][t], acc);
            acc = fmaf(al.w, gls[j4*4 + 3][t], acc);
        }
        Xout[(size_t)(b*NN + i)*D1 + h*HID + t] = fmaxf(acc + bv, 0.f);
    }
}

// -------- head layer 1 as GEMM with fused gather --------
// QH/VH(128, 256) = relu(Xc(128, 1152) @ W(1152, 256) + b)
// grid (4, 16): x = 32-batch tile; y<8 -> q cols y*32, else v cols (y-8)*32
__global__ void head1_k(const float* __restrict__ obs,
                        const float* __restrict__ X0, const float* __restrict__ X1,
                        const float* __restrict__ X2,
                        const float* __restrict__ qw1, const float* __restrict__ qb1,
                        const float* __restrict__ vw1, const float* __restrict__ vb1,
                        float* __restrict__ QH, float* __restrict__ VH)
{
    __shared__ float Xs[32][65];
    __shared__ int s_a[32];

    int mt = blockIdx.x;
    int y  = blockIdx.y;
    const float* W  = (y < 8) ? qw1 : vw1;
    const float* Bv = (y < 8) ? qb1 : vb1;
    float* O        = (y < 8) ? QH  : VH;
    int col0 = (y & 7) * 32;

    int t = threadIdx.x;          // 256
    int col = col0 + (t & 31);
    int rr  = (t >> 5) * 4;

    if (t < 32) {
        float av = obs[(size_t)(mt*32 + t)*OBS_W + (OBS_W - 1)];
        s_a[t] = (int)fminf(fmaxf(av, 0.f), 31.f);
    }
    __syncthreads();

    float acc[4] = {0.f, 0.f, 0.f, 0.f};

    for (int kb = 0; kb < LATENT; kb += 64) {
        __syncthreads();
        #pragma unroll
        for (int idx = t; idx < 32*64; idx += 256) {
            int r = idx >> 6, c = idx & 63;
            int k = kb + c;
            int a = s_a[r];
            int brow = (mt*32 + r)*NN + a;
            float v;
            if (k < HID)            v = X0[(size_t)brow*HID + k];
            else if (k < HID + D1)  v = X1[(size_t)brow*D1 + (k - HID)];
            else                    v = X2[(size_t)brow*D1 + (k - HID - D1)];
            Xs[r][c] = v;
        }
        __syncthreads();
        #pragma unroll 4
        for (int k = 0; k < 64; k++) {
            float wv = W[(size_t)(kb + k)*DUEL_H + col];
            acc[0] = fmaf(Xs[rr + 0][k], wv, acc[0]);
            acc[1] = fmaf(Xs[rr + 1][k], wv, acc[1]);
            acc[2] = fmaf(Xs[rr + 2][k], wv, acc[2]);
            acc[3] = fmaf(Xs[rr + 3][k], wv, acc[3]);
        }
    }

    float bias = Bv[col];
    #pragma unroll
    for (int i = 0; i < 4; i++)
        O[(size_t)(mt*32 + rr + i)*DUEL_H + col] = fmaxf(acc[i] + bias, 0.f);
}

// -------- head layer 2 + dueling combine: one block per batch --------
__global__ void head2_k(const float* __restrict__ QH, const float* __restrict__ VH,
                        const float* __restrict__ qw2, const float* __restrict__ qb2,
                        const float* __restrict__ vw2, const float* __restrict__ vb2,
                        float* __restrict__ out)
{
    __shared__ float res[6];
    int b = blockIdx.x, t = threadIdx.x; // 192 threads = 6 warps
    int w = t >> 5, l = t & 31;

    float s = 0.f;
    if (w < OUTD) {
        #pragma unroll
        for (int k = l; k < DUEL_H; k += 32)
            s = fmaf(QH[b*DUEL_H + k], qw2[k*OUTD + w], s);
    } else {
        #pragma unroll
        for (int k = l; k < DUEL_H; k += 32)
            s = fmaf(VH[b*DUEL_H + k], vw2[k], s);
    }
    #pragma unroll
    for (int o = 16; o > 0; o >>= 1) s += __shfl_xor_sync(0xffffffffu, s, o);
    if (l == 0) res[w] = s + ((w < OUTD) ? qb2[w] : vb2[0]);
    __syncthreads();

    if (t < OUTD) {
        float m = (res[0] + res[1] + res[2] + res[3] + res[4]) * 0.2f;
        out[b*OUTD + t] = res[t] - m + res[5];
    }
}

extern "C" void kernel_launch(void* const* d_in, const int* in_sizes, int n_in,
                              void* d_out, int out_size)
{
    const float* obs    = (const float*)d_in[0];
    const float* enc_w1 = (const float*)d_in[1];
    const float* enc_b1 = (const float*)d_in[2];
    const float* enc_w2 = (const float*)d_in[3];
    const float* enc_b2 = (const float*)d_in[4];
    const float* wl1    = (const float*)d_in[5];
    const float* wr1    = (const float*)d_in[6];
    const float* att1   = (const float*)d_in[7];
    const float* bias1  = (const float*)d_in[8];
    const float* wl2    = (const float*)d_in[9];
    const float* wr2    = (const float*)d_in[10];
    const float* att2   = (const float*)d_in[11];
    const float* bias2  = (const float*)d_in[12];
    const float* q_w1   = (const float*)d_in[13];
    const float* q_b1   = (const float*)d_in[14];
    const float* q_w2   = (const float*)d_in[15];
    const float* q_b2   = (const float*)d_in[16];
    const float* v_w1   = (const float*)d_in[17];
    const float* v_b1   = (const float*)d_in[18];
    const float* v_w2   = (const float*)d_in[19];
    const float* v_b2   = (const float*)d_in[20];
    float* out = (float*)d_out;

    float* X0;  cudaGetSymbolAddress((void**)&X0,  g_X0);
    unsigned* ADJ; cudaGetSymbolAddress((void**)&ADJ, g_ADJ);
    float* GL1; cudaGetSymbolAddress((void**)&GL1, g_GL1);
    float* GR1; cudaGetSymbolAddress((void**)&GR1, g_GR1);
    float* X1;  cudaGetSymbolAddress((void**)&X1,  g_X1);
    float* GL2; cudaGetSymbolAddress((void**)&GL2, g_GL2);
    float* GR2; cudaGetSymbolAddress((void**)&GR2, g_GR2);
    float* X2;  cudaGetSymbolAddress((void**)&X2,  g_X2);
    float* QH;  cudaGetSymbolAddress((void**)&QH,  g_QH);
    float* VH;  cudaGetSymbolAddress((void**)&VH,  g_VH);

    enc_kernel<<<BS, 128>>>(obs, enc_w1, enc_b1, enc_w2, enc_b2, X0, ADJ);

    gat_gemm<HID><<<dim3(32, 8), 256>>>(X0, wl1, wr1, GL1, GR1);
    attn_k<<<dim3(BS, HEADS), 128>>>(GL1, GR1, ADJ, att1, bias1, X1);

    gat_gemm<D1><<<dim3(32, 8), 256>>>(X1, wl2, wr2, GL2, GR2);
    attn_k<<<dim3(BS, HEADS), 128>>>(GL2, GR2, ADJ, att2, bias2, X2);

    head1_k<<<dim3(4, 16), 256>>>(obs, X0, X1, X2,
                                  q_w1, q_b1, v_w1, v_b1, QH, VH);
    head2_k<<<BS, 192>>>(QH, VH, q_w2, q_b2, v_w2, v_b2, out);
}

// round 5
// speedup vs baseline: 1.0459x; 1.0196x over previous
#include <cuda_runtime.h>
#include <cuda_bf16.h>

#define BS 128
#define NN 32
#define IN_DIM 16
#define HID 128
#define HEADS 4
#define OUTD 5
#define DUEL_H 256
#define D1 (HEADS*HID)       // 512
#define LATENT (HID + 2*D1)  // 1152
#define OBS_W (NN*(2+IN_DIM)+1) // 577
#define RAD2 0.09f

typedef unsigned long long ull;

__device__ __forceinline__ ull pack2(float v) {
    ull r; asm("mov.b64 %0, {%1, %1};" : "=l"(r) : "f"(v)); return r;
}
__device__ __forceinline__ void fma2(ull& d, ull a, ull b) {
    asm("fma.rn.f32x2 %0, %1, %2, %0;" : "+l"(d) : "l"(a), "l"(b));
}
__device__ __forceinline__ float2 unpack2(ull v) {
    float2 r; asm("mov.b64 {%0, %1}, %2;" : "=f"(r.x), "=f"(r.y) : "l"(v)); return r;
}

// -------- scratch (device globals; no runtime alloc allowed) --------
__device__ float g_X0 [BS*NN*HID];
__device__ unsigned g_ADJ[BS*NN];
__device__ float g_GL1[BS*NN*D1];
__device__ float g_GR1[BS*NN*D1];
__device__ float g_X1 [BS*NN*D1];
__device__ float g_GL2[BS*NN*D1];
__device__ float g_GR2[BS*NN*D1];
__device__ float g_X2 [BS*NN*D1];
__device__ float g_QH [BS*DUEL_H];
__device__ float g_VH [BS*DUEL_H];

// -------- encoder + adjacency: one block per batch, 128 threads --------
__global__ void enc_kernel(const float* __restrict__ obs,
                           const float* __restrict__ w1, const float* __restrict__ b1,
                           const float* __restrict__ w2, const float* __restrict__ b2,
                           float* __restrict__ X0, unsigned* __restrict__ ADJ)
{
    __shared__ float s_obs[OBS_W];
    __shared__ float s_h[NN*HID];
    int b = blockIdx.x, t = threadIdx.x;

    for (int i = t; i < OBS_W; i += 128) s_obs[i] = obs[b*OBS_W + i];
    __syncthreads();

    if (t < NN) {
        float xi = s_obs[t*18 + 0], yi = s_obs[t*18 + 1];
        unsigned m = 0;
        #pragma unroll
        for (int j = 0; j < NN; j++) {
            float dx = xi - s_obs[j*18 + 0];
            float dy = yi - s_obs[j*18 + 1];
            float d2 = dx*dx + dy*dy;
            if (d2 < RAD2 || j == t) m |= (1u << j);
        }
        ADJ[b*NN + t] = m;
    }

    float bb = b1[t];
    for (int r = 0; r < NN; r++) {
        float acc = bb;
        #pragma unroll
        for (int f = 0; f < IN_DIM; f++)
            acc += s_obs[r*18 + 2 + f] * w1[f*HID + t];
        s_h[r*HID + t] = fmaxf(acc, 0.f);
    }
    __syncthreads();

    float b2v = b2[t];
    for (int r = 0; r < NN; r++) {
        float acc = b2v;
        #pragma unroll 8
        for (int k = 0; k < HID; k++)
            acc += s_h[r*HID + k] * w2[k*HID + t];
        X0[(b*NN + r)*HID + t] = fmaxf(acc, 0.f);
    }
}

// -------- fused GL/GR GEMM, LDS-lean row-pair f32x2 --------
// Y(4096, 512) = X(4096, DIN) @ W(DIN, 512), W in {WL, WR}.
// grid (64, 8): x = 64-row M tile; y<4 -> WL cols y*128, else WR cols (y-4)*128.
// block 128 threads; thread computes 8 rows (4 f32x2 row-pairs) x 8 cols.
template<int DIN>
__global__ void __launch_bounds__(128, 4)
gat_gemm(const float* __restrict__ X,
         const float* __restrict__ WL, const float* __restrict__ WR,
         float* __restrict__ GL, float* __restrict__ GR)
{
    __shared__ float Xs[32][68];    // transposed: Xs[k][r], 16B-aligned rows
    __shared__ float Ws[32][132];

    int mt = blockIdx.x;
    int yt = blockIdx.y;
    const float* W = (yt < 4) ? WL : WR;
    float* Y = (yt < 4) ? GL : GR;
    int ct = (yt & 3) * 128;

    int t  = threadIdx.x;
    int tx = t & 15, ty = t >> 4;   // ty 0..7
    int r0 = ty * 8;
    int c0 = tx * 8;

    ull acc[4][8];
    #pragma unroll
    for (int rp = 0; rp < 4; rp++)
        #pragma unroll
        for (int c = 0; c < 8; c++) acc[rp][c] = 0ull;

    const float* Xblk = X + (size_t)(mt*64) * DIN;

    for (int kb = 0; kb < DIN; kb += 32) {
        // X tile 64 rows x 32 k, stored TRANSPOSED: Xs[k][r]
        #pragma unroll
        for (int f = t; f < 512; f += 128) {          // 512 float4 reads
            int r = f >> 3, c4 = f & 7;
            float4 v = *(const float4*)(Xblk + r*DIN + kb + c4*4);
            Xs[c4*4 + 0][r] = v.x;
            Xs[c4*4 + 1][r] = v.y;
            Xs[c4*4 + 2][r] = v.z;
            Xs[c4*4 + 3][r] = v.w;
        }
        // W tile 32 x 128
        #pragma unroll
        for (int f = t; f < 1024; f += 128) {         // 1024 float4
            int r = f >> 5, c4 = f & 31;
            *(float4*)&Ws[r][c4*4] =
                *(const float4*)(W + (size_t)(kb + r)*D1 + ct + c4*4);
        }
        __syncthreads();

        #pragma unroll 16
        for (int k = 0; k < 32; k++) {
            // 8 consecutive X rows = 4 packed row-pairs, 2 LDS.128
            const ull* xp = (const ull*)&Xs[k][r0];
            ull x0 = xp[0], x1 = xp[1], x2 = xp[2], x3 = xp[3];
            float4 wA = *(const float4*)&Ws[k][c0];
            float4 wB = *(const float4*)&Ws[k][c0 + 4];
            ull W0 = pack2(wA.x), W1 = pack2(wA.y), W2 = pack2(wA.z), W3 = pack2(wA.w);
            ull W4 = pack2(wB.x), W5 = pack2(wB.y), W6 = pack2(wB.z), W7 = pack2(wB.w);
            fma2(acc[0][0], x0, W0); fma2(acc[0][1], x0, W1);
            fma2(acc[0][2], x0, W2); fma2(acc[0][3], x0, W3);
            fma2(acc[0][4], x0, W4); fma2(acc[0][5], x0, W5);
            fma2(acc[0][6], x0, W6); fma2(acc[0][7], x0, W7);
            fma2(acc[1][0], x1, W0); fma2(acc[1][1], x1, W1);
            fma2(acc[1][2], x1, W2); fma2(acc[1][3], x1, W3);
            fma2(acc[1][4], x1, W4); fma2(acc[1][5], x1, W5);
            fma2(acc[1][6], x1, W6); fma2(acc[1][7], x1, W7);
            fma2(acc[2][0], x2, W0); fma2(acc[2][1], x2, W1);
            fma2(acc[2][2], x2, W2); fma2(acc[2][3], x2, W3);
            fma2(acc[2][4], x2, W4); fma2(acc[2][5], x2, W5);
            fma2(acc[2][6], x2, W6); fma2(acc[2][7], x2, W7);
            fma2(acc[3][0], x3, W0); fma2(acc[3][1], x3, W1);
            fma2(acc[3][2], x3, W2); fma2(acc[3][3], x3, W3);
            fma2(acc[3][4], x3, W4); fma2(acc[3][5], x3, W5);
            fma2(acc[3][6], x3, W6); fma2(acc[3][7], x3, W7);
        }
        __syncthreads();
    }

    #pragma unroll
    for (int rp = 0; rp < 4; rp++) {
        float2 u[8];
        #pragma unroll
        for (int c = 0; c < 8; c++) u[c] = unpack2(acc[rp][c]);
        int row = mt*64 + r0 + 2*rp;
        float4 a0 = make_float4(u[0].x, u[1].x, u[2].x, u[3].x);
        float4 a1 = make_float4(u[4].x, u[5].x, u[6].x, u[7].x);
        float4 b0 = make_float4(u[0].y, u[1].y, u[2].y, u[3].y);
        float4 b1 = make_float4(u[4].y, u[5].y, u[6].y, u[7].y);
        *(float4*)(Y + (size_t)row*D1 + ct + c0)           = a0;
        *(float4*)(Y + (size_t)row*D1 + ct + c0 + 4)       = a1;
        *(float4*)(Y + (size_t)(row+1)*D1 + ct + c0)       = b0;
        *(float4*)(Y + (size_t)(row+1)*D1 + ct + c0 + 4)   = b1;
    }
}

// -------- GATv2 attention per (batch, head) --------
__global__ void attn_k(const float* __restrict__ GL, const float* __restrict__ GR,
                       const unsigned* __restrict__ ADJ,
                       const float* __restrict__ att, const float* __restrict__ bias,
                       float* __restrict__ Xout)
{
    __shared__ float gls[NN][132];
    __shared__ float grs[NN][132];
    __shared__ float lg[NN*NN];
    __shared__ float attv[HID];

    int b = blockIdx.x, h = blockIdx.y, t = threadIdx.x; // 128 threads
    int w = t >> 5, j = t & 31;

    attv[t] = att[h*HID + t];
    #pragma unroll
    for (int i = t; i < NN*(HID/4); i += 128) {
        int r = i >> 5, c4 = i & 31;
        const float* src = GL + (size_t)(b*NN + r)*D1 + h*HID + c4*4;
        const float* srr = GR + (size_t)(b*NN + r)*D1 + h*HID + c4*4;
        *(float4*)&gls[r][c4*4] = *(const float4*)src;
        *(float4*)&grs[r][c4*4] = *(const float4*)srr;
    }
    __syncthreads();

    #pragma unroll
    for (int ii = 0; ii < 8; ii++) {
        int i = w*8 + ii;
        unsigned m = ADJ[b*NN + i];
        float acc = 0.f;
        #pragma unroll 8
        for (int c4 = 0; c4 < 32; c4++) {
            float4 gr4 = *(const float4*)&grs[i][c4*4];
            float4 gl4 = *(const float4*)&gls[j][c4*4];
            float4 a4  = *(const float4*)&attv[c4*4];
            float v;
            v = gr4.x + gl4.x; v = v - 0.8f*fminf(v, 0.f); acc = fmaf(a4.x, v, acc);
            v = gr4.y + gl4.y; v = v - 0.8f*fminf(v, 0.f); acc = fmaf(a4.y, v, acc);
            v = gr4.z + gl4.z; v = v - 0.8f*fminf(v, 0.f); acc = fmaf(a4.z, v, acc);
            v = gr4.w + gl4.w; v = v - 0.8f*fminf(v, 0.f); acc = fmaf(a4.w, v, acc);
        }
        lg[i*NN + j] = ((m >> j) & 1u) ? acc : -1e30f;
    }
    __syncthreads();

    #pragma unroll
    for (int ii = 0; ii < 8; ii++) {
        int i = w*8 + ii;
        float x = lg[i*NN + j];
        float mx = x;
        #pragma unroll
        for (int o = 16; o > 0; o >>= 1) mx = fmaxf(mx, __shfl_xor_sync(0xffffffffu, mx, o));
        float e = __expf(x - mx);
        float s = e;
        #pragma unroll
        for (int o = 16; o > 0; o >>= 1) s += __shfl_xor_sync(0xffffffffu, s, o);
        lg[i*NN + j] = e / s;
    }
    __syncthreads();

    float bv = bias[h*HID + t];
    #pragma unroll 4
    for (int i = 0; i < NN; i++) {
        float acc = 0.f;
        #pragma unroll
        for (int j4 = 0; j4 < 8; j4++) {
            float4 al = *(const float4*)&lg[i*NN + j4*4];
            acc = fmaf(al.x, gls[j4*4 + 0][t], acc);
            acc = fmaf(al.y, gls[j4*4 + 1][t], acc);
            acc = fmaf(al.z, gls[j4*4 + 2][t], acc);
            acc = fmaf(al.w, gls[j4*4 + 3][t], acc);
        }
        Xout[(size_t)(b*NN + i)*D1 + h*HID + t] = fmaxf(acc + bv, 0.f);
    }
}

// -------- head layer 1 as GEMM with fused gather --------
__global__ void head1_k(const float* __restrict__ obs,
                        const float* __restrict__ X0, const float* __restrict__ X1,
                        const float* __restrict__ X2,
                        const float* __restrict__ qw1, const float* __restrict__ qb1,
                        const float* __restrict__ vw1, const float* __restrict__ vb1,
                        float* __restrict__ QH, float* __restrict__ VH)
{
    __shared__ float Xs[32][65];
    __shared__ int s_a[32];

    int mt = blockIdx.x;
    int y  = blockIdx.y;
    const float* W  = (y < 8) ? qw1 : vw1;
    const float* Bv = (y < 8) ? qb1 : vb1;
    float* O        = (y < 8) ? QH  : VH;
    int col0 = (y & 7) * 32;

    int t = threadIdx.x;
    int col = col0 + (t & 31);
    int rr  = (t >> 5) * 4;

    if (t < 32) {
        float av = obs[(size_t)(mt*32 + t)*OBS_W + (OBS_W - 1)];
        s_a[t] = (int)fminf(fmaxf(av, 0.f), 31.f);
    }
    __syncthreads();

    float acc[4] = {0.f, 0.f, 0.f, 0.f};

    for (int kb = 0; kb < LATENT; kb += 64) {
        __syncthreads();
        #pragma unroll
        for (int idx = t; idx < 32*64; idx += 256) {
            int r = idx >> 6, c = idx & 63;
            int k = kb + c;
            int a = s_a[r];
            int brow = (mt*32 + r)*NN + a;
            float v;
            if (k < HID)            v = X0[(size_t)brow*HID + k];
            else if (k < HID + D1)  v = X1[(size_t)brow*D1 + (k - HID)];
            else                    v = X2[(size_t)brow*D1 + (k - HID - D1)];
            Xs[r][c] = v;
        }
        __syncthreads();
        #pragma unroll 4
        for (int k = 0; k < 64; k++) {
            float wv = W[(size_t)(kb + k)*DUEL_H + col];
            acc[0] = fmaf(Xs[rr + 0][k], wv, acc[0]);
            acc[1] = fmaf(Xs[rr + 1][k], wv, acc[1]);
            acc[2] = fmaf(Xs[rr + 2][k], wv, acc[2]);
            acc[3] = fmaf(Xs[rr + 3][k], wv, acc[3]);
        }
    }

    float bias = Bv[col];
    #pragma unroll
    for (int i = 0; i < 4; i++)
        O[(size_t)(mt*32 + rr + i)*DUEL_H + col] = fmaxf(acc[i] + bias, 0.f);
}

// -------- head layer 2 + dueling combine --------
__global__ void head2_k(const float* __restrict__ QH, const float* __restrict__ VH,
                        const float* __restrict__ qw2, const float* __restrict__ qb2,
                        const float* __restrict__ vw2, const float* __restrict__ vb2,
                        float* __restrict__ out)
{
    __shared__ float res[6];
    int b = blockIdx.x, t = threadIdx.x; // 192 threads
    int w = t >> 5, l = t & 31;

    float s = 0.f;
    if (w < OUTD) {
        #pragma unroll
        for (int k = l; k < DUEL_H; k += 32)
            s = fmaf(QH[b*DUEL_H + k], qw2[k*OUTD + w], s);
    } else {
        #pragma unroll
        for (int k = l; k < DUEL_H; k += 32)
            s = fmaf(VH[b*DUEL_H + k], vw2[k], s);
    }
    #pragma unroll
    for (int o = 16; o > 0; o >>= 1) s += __shfl_xor_sync(0xffffffffu, s, o);
    if (l == 0) res[w] = s + ((w < OUTD) ? qb2[w] : vb2[0]);
    __syncthreads();

    if (t < OUTD) {
        float m = (res[0] + res[1] + res[2] + res[3] + res[4]) * 0.2f;
        out[b*OUTD + t] = res[t] - m + res[5];
    }
}

extern "C" void kernel_launch(void* const* d_in, const int* in_sizes, int n_in,
                              void* d_out, int out_size)
{
    const float* obs    = (const float*)d_in[0];
    const float* enc_w1 = (const float*)d_in[1];
    const float* enc_b1 = (const float*)d_in[2];
    const float* enc_w2 = (const float*)d_in[3];
    const float* enc_b2 = (const float*)d_in[4];
    const float* wl1    = (const float*)d_in[5];
    const float* wr1    = (const float*)d_in[6];
    const float* att1   = (const float*)d_in[7];
    const float* bias1  = (const float*)d_in[8];
    const float* wl2    = (const float*)d_in[9];
    const float* wr2    = (const float*)d_in[10];
    const float* att2   = (const float*)d_in[11];
    const float* bias2  = (const float*)d_in[12];
    const float* q_w1   = (const float*)d_in[13];
    const float* q_b1   = (const float*)d_in[14];
    const float* q_w2   = (const float*)d_in[15];
    const float* q_b2   = (const float*)d_in[16];
    const float* v_w1   = (const float*)d_in[17];
    const float* v_b1   = (const float*)d_in[18];
    const float* v_w2   = (const float*)d_in[19];
    const float* v_b2   = (const float*)d_in[20];
    float* out = (float*)d_out;

    float* X0;  cudaGetSymbolAddress((void**)&X0,  g_X0);
    unsigned* ADJ; cudaGetSymbolAddress((void**)&ADJ, g_ADJ);
    float* GL1; cudaGetSymbolAddress((void**)&GL1, g_GL1);
    float* GR1; cudaGetSymbolAddress((void**)&GR1, g_GR1);
    float* X1;  cudaGetSymbolAddress((void**)&X1,  g_X1);
    float* GL2; cudaGetSymbolAddress((void**)&GL2, g_GL2);
    float* GR2; cudaGetSymbolAddress((void**)&GR2, g_GR2);
    float* X2;  cudaGetSymbolAddress((void**)&X2,  g_X2);
    float* QH;  cudaGetSymbolAddress((void**)&QH,  g_QH);
    float* VH;  cudaGetSymbolAddress((void**)&VH,  g_VH);

    enc_kernel<<<BS, 128>>>(obs, enc_w1, enc_b1, enc_w2, enc_b2, X0, ADJ);

    gat_gemm<HID><<<dim3(64, 8), 128>>>(X0, wl1, wr1, GL1, GR1);
    attn_k<<<dim3(BS, HEADS), 128>>>(GL1, GR1, ADJ, att1, bias1, X1);

    gat_gemm<D1><<<dim3(64, 8), 128>>>(X1, wl2, wr2, GL2, GR2);
    attn_k<<<dim3(BS, HEADS), 128>>>(GL2, GR2, ADJ, att2, bias2, X2);

    head1_k<<<dim3(4, 16), 256>>>(obs, X0, X1, X2,
                                  q_w1, q_b1, v_w1, v_b1, QH, VH);
    head2_k<<<BS, 192>>>(QH, VH, q_w2, q_b2, v_w2, v_b2, out);
}